// round 1
// baseline (speedup 1.0000x reference)
#include <cuda_runtime.h>

// Problem constants (fixed shapes for MoLModel_20899310862740)
#define M_TOK 8192          // Bt*S = 4*2048
#define DIN   4096
#define DOUT  4096
#define NE    8             // experts
#define DKD   32            // d_k
#define RK    16            // lora rank
#define EQ    (NE*DKD)      // 256
#define ER    (NE*RK)       // 128
#define SCALING 1.0f
#define INV_SQRT_DK 0.17677669529663687f

// Scratch (no cudaMalloc allowed) — ~25 MB total
__device__ float g_qbuf[(size_t)M_TOK*EQ];
__device__ float g_kbuf[(size_t)M_TOK*EQ];
__device__ float g_hbuf[(size_t)M_TOK*ER];
__device__ float g_gbuf[(size_t)M_TOK*ER];

// ---------------------------------------------------------------------------
// Generic C[M,N] = A[M,K] @ B[N,K]^T   (both row-major, K contiguous)
// BM=BN=128, BK=16, 256 threads, each thread computes 8x8.
// ---------------------------------------------------------------------------
template<int BM, int BN, int BK, int TM, int TN>
__global__ __launch_bounds__(256)
void sgemm_nt(const float* __restrict__ A, const float* __restrict__ B,
              float* __restrict__ C, int M, int N, int K) {
    __shared__ __align__(16) float As[BK][BM];
    __shared__ __align__(16) float Bs[BK][BN];
    const int bm = blockIdx.y * BM;
    const int bn = blockIdx.x * BN;
    const int tid = threadIdx.x;
    const int tr = tid / 16;      // 0..15
    const int tc = tid % 16;      // 0..15

    float acc[TM][TN];
    #pragma unroll
    for (int i = 0; i < TM; i++)
        #pragma unroll
        for (int j = 0; j < TN; j++) acc[i][j] = 0.f;

    constexpr int LOADS = (BM * BK) / (256 * 4);   // float4 loads/thread/tile

    for (int k0 = 0; k0 < K; k0 += BK) {
        #pragma unroll
        for (int l = 0; l < LOADS; l++) {
            int li  = tid + l * 256;
            int row = li / (BK / 4);
            int c4  = li % (BK / 4);
            float4 v = *(const float4*)(A + (size_t)(bm + row) * K + k0 + c4 * 4);
            As[c4*4+0][row] = v.x; As[c4*4+1][row] = v.y;
            As[c4*4+2][row] = v.z; As[c4*4+3][row] = v.w;
        }
        #pragma unroll
        for (int l = 0; l < LOADS; l++) {
            int li  = tid + l * 256;
            int row = li / (BK / 4);
            int c4  = li % (BK / 4);
            float4 v = *(const float4*)(B + (size_t)(bn + row) * K + k0 + c4 * 4);
            Bs[c4*4+0][row] = v.x; Bs[c4*4+1][row] = v.y;
            Bs[c4*4+2][row] = v.z; Bs[c4*4+3][row] = v.w;
        }
        __syncthreads();
        #pragma unroll
        for (int k = 0; k < BK; k++) {
            float ar[TM], br[TN];
            float4 a0 = *(const float4*)&As[k][tr*TM];
            float4 a1 = *(const float4*)&As[k][tr*TM+4];
            ar[0]=a0.x; ar[1]=a0.y; ar[2]=a0.z; ar[3]=a0.w;
            ar[4]=a1.x; ar[5]=a1.y; ar[6]=a1.z; ar[7]=a1.w;
            float4 b0 = *(const float4*)&Bs[k][tc*TN];
            float4 b1 = *(const float4*)&Bs[k][tc*TN+4];
            br[0]=b0.x; br[1]=b0.y; br[2]=b0.z; br[3]=b0.w;
            br[4]=b1.x; br[5]=b1.y; br[6]=b1.z; br[7]=b1.w;
            #pragma unroll
            for (int i = 0; i < TM; i++)
                #pragma unroll
                for (int j = 0; j < TN; j++)
                    acc[i][j] += ar[i] * br[j];
        }
        __syncthreads();
    }

    #pragma unroll
    for (int i = 0; i < TM; i++) {
        float* crow = C + (size_t)(bm + tr*TM + i) * N + bn + tc*TN;
        #pragma unroll
        for (int j = 0; j < TN; j += 4) {
            float4 v = {acc[i][j], acc[i][j+1], acc[i][j+2], acc[i][j+3]};
            *(float4*)(crow + j) = v;
        }
    }
}

// ---------------------------------------------------------------------------
// Per-token routing: scores = (q·k)/sqrt(dk), softmax over E, g = w*h*SCALING
// One warp per token.
// ---------------------------------------------------------------------------
__global__ __launch_bounds__(256)
void softmax_gate_kernel() {
    int gwarp = (blockIdx.x * blockDim.x + threadIdx.x) >> 5;
    int lane  = threadIdx.x & 31;
    if (gwarp >= M_TOK) return;

    const float* q = g_qbuf + (size_t)gwarp * EQ;
    const float* k = g_kbuf + (size_t)gwarp * EQ;

    float s[NE];
    #pragma unroll
    for (int e = 0; e < NE; e++) {
        float v = q[e*DKD + lane] * k[e*DKD + lane];
        #pragma unroll
        for (int o = 16; o > 0; o >>= 1)
            v += __shfl_xor_sync(0xffffffffu, v, o);
        s[e] = v * INV_SQRT_DK;
    }
    float m = s[0];
    #pragma unroll
    for (int e = 1; e < NE; e++) m = fmaxf(m, s[e]);
    float sum = 0.f;
    #pragma unroll
    for (int e = 0; e < NE; e++) { s[e] = expf(s[e] - m); sum += s[e]; }
    float inv = 1.f / sum;

    const float* h = g_hbuf + (size_t)gwarp * ER;
    float*       g = g_gbuf + (size_t)gwarp * ER;
    #pragma unroll
    for (int j = 0; j < 4; j++) {
        int er = lane * 4 + j;          // 0..127
        int e  = er >> 4;               // er / RK
        g[er] = s[e] * inv * h[er] * SCALING;
    }
}

// ---------------------------------------------------------------------------
// out[t,o] = b[o] + x[t,:]·W[o,:] + sum_{e,r} g[t,e*16+r]*Bm[e,o,r]
// Same tiling as sgemm_nt; K = 4096 main + 8 expert tiles of 16.
// ---------------------------------------------------------------------------
__global__ __launch_bounds__(256)
void out_kernel(const float* __restrict__ x, const float* __restrict__ W,
                const float* __restrict__ bias, const float* __restrict__ Bm,
                float* __restrict__ out) {
    constexpr int BM = 128, BN = 128, BK = 16, TM = 8, TN = 8;
    __shared__ __align__(16) float As[BK][BM];
    __shared__ __align__(16) float Bs[BK][BN];
    const int bm = blockIdx.y * BM;
    const int bn = blockIdx.x * BN;
    const int tid = threadIdx.x;
    const int tr = tid / 16, tc = tid % 16;

    float acc[TM][TN];
    #pragma unroll
    for (int i = 0; i < TM; i++)
        #pragma unroll
        for (int j = 0; j < TN; j++) acc[i][j] = 0.f;

    constexpr int LOADS = (BM * BK) / (256 * 4);   // = 2

    // Phase 1: x @ W^T over K = DIN
    for (int k0 = 0; k0 < DIN; k0 += BK) {
        #pragma unroll
        for (int l = 0; l < LOADS; l++) {
            int li = tid + l * 256;
            int row = li / 4, c4 = li % 4;
            float4 v = *(const float4*)(x + (size_t)(bm + row) * DIN + k0 + c4 * 4);
            As[c4*4+0][row] = v.x; As[c4*4+1][row] = v.y;
            As[c4*4+2][row] = v.z; As[c4*4+3][row] = v.w;
        }
        #pragma unroll
        for (int l = 0; l < LOADS; l++) {
            int li = tid + l * 256;
            int row = li / 4, c4 = li % 4;
            float4 v = *(const float4*)(W + (size_t)(bn + row) * DIN + k0 + c4 * 4);
            Bs[c4*4+0][row] = v.x; Bs[c4*4+1][row] = v.y;
            Bs[c4*4+2][row] = v.z; Bs[c4*4+3][row] = v.w;
        }
        __syncthreads();
        #pragma unroll
        for (int k = 0; k < BK; k++) {
            float ar[TM], br[TN];
            float4 a0 = *(const float4*)&As[k][tr*TM];
            float4 a1 = *(const float4*)&As[k][tr*TM+4];
            ar[0]=a0.x; ar[1]=a0.y; ar[2]=a0.z; ar[3]=a0.w;
            ar[4]=a1.x; ar[5]=a1.y; ar[6]=a1.z; ar[7]=a1.w;
            float4 b0 = *(const float4*)&Bs[k][tc*TN];
            float4 b1 = *(const float4*)&Bs[k][tc*TN+4];
            br[0]=b0.x; br[1]=b0.y; br[2]=b0.z; br[3]=b0.w;
            br[4]=b1.x; br[5]=b1.y; br[6]=b1.z; br[7]=b1.w;
            #pragma unroll
            for (int i = 0; i < TM; i++)
                #pragma unroll
                for (int j = 0; j < TN; j++)
                    acc[i][j] += ar[i] * br[j];
        }
        __syncthreads();
    }

    // Phase 2: g @ Bm^T, one 16-wide K-tile per expert.
    // Bm[e, o, r] with r contiguous (16 floats) -> float4 loads OK.
    for (int e = 0; e < NE; e++) {
        #pragma unroll
        for (int l = 0; l < LOADS; l++) {
            int li = tid + l * 256;
            int row = li / 4, c4 = li % 4;
            float4 v = *(const float4*)(g_gbuf + (size_t)(bm + row) * ER + e * RK + c4 * 4);
            As[c4*4+0][row] = v.x; As[c4*4+1][row] = v.y;
            As[c4*4+2][row] = v.z; As[c4*4+3][row] = v.w;
        }
        #pragma unroll
        for (int l = 0; l < LOADS; l++) {
            int li = tid + l * 256;
            int row = li / 4, c4 = li % 4;
            float4 v = *(const float4*)(Bm + ((size_t)e * DOUT + bn + row) * RK + c4 * 4);
            Bs[c4*4+0][row] = v.x; Bs[c4*4+1][row] = v.y;
            Bs[c4*4+2][row] = v.z; Bs[c4*4+3][row] = v.w;
        }
        __syncthreads();
        #pragma unroll
        for (int k = 0; k < BK; k++) {
            float ar[TM], br[TN];
            float4 a0 = *(const float4*)&As[k][tr*TM];
            float4 a1 = *(const float4*)&As[k][tr*TM+4];
            ar[0]=a0.x; ar[1]=a0.y; ar[2]=a0.z; ar[3]=a0.w;
            ar[4]=a1.x; ar[5]=a1.y; ar[6]=a1.z; ar[7]=a1.w;
            float4 b0 = *(const float4*)&Bs[k][tc*TN];
            float4 b1 = *(const float4*)&Bs[k][tc*TN+4];
            br[0]=b0.x; br[1]=b0.y; br[2]=b0.z; br[3]=b0.w;
            br[4]=b1.x; br[5]=b1.y; br[6]=b1.z; br[7]=b1.w;
            #pragma unroll
            for (int i = 0; i < TM; i++)
                #pragma unroll
                for (int j = 0; j < TN; j++)
                    acc[i][j] += ar[i] * br[j];
        }
        __syncthreads();
    }

    // Epilogue: + bias, store
    #pragma unroll
    for (int i = 0; i < TM; i++) {
        float* orow = out + (size_t)(bm + tr*TM + i) * DOUT + bn + tc*TN;
        const float* brow = bias + bn + tc*TN;
        #pragma unroll
        for (int j = 0; j < TN; j += 4) {
            float4 v = {acc[i][j]   + brow[j],
                        acc[i][j+1] + brow[j+1],
                        acc[i][j+2] + brow[j+2],
                        acc[i][j+3] + brow[j+3]};
            *(float4*)(orow + j) = v;
        }
    }
}

// ---------------------------------------------------------------------------
extern "C" void kernel_launch(void* const* d_in, const int* in_sizes, int n_in,
                              void* d_out, int out_size) {
    const float* x  = (const float*)d_in[0];
    const float* W  = (const float*)d_in[1];
    const float* b  = (const float*)d_in[2];
    const float* Wq = (const float*)d_in[3];
    const float* Wk = (const float*)d_in[4];
    const float* A  = (const float*)d_in[5];   // [E,R,Din] == [128,4096]
    const float* Bm = (const float*)d_in[6];   // [E,Dout,R]
    float* out = (float*)d_out;

    float *qb, *kb, *hb;
    cudaGetSymbolAddress((void**)&qb, g_qbuf);
    cudaGetSymbolAddress((void**)&kb, g_kbuf);
    cudaGetSymbolAddress((void**)&hb, g_hbuf);

    // Projections: q, k [8192,256]; h [8192,128]
    sgemm_nt<128,128,16,8,8><<<dim3(EQ/128, M_TOK/128), 256>>>(x, Wq, qb, M_TOK, EQ, DIN);
    sgemm_nt<128,128,16,8,8><<<dim3(EQ/128, M_TOK/128), 256>>>(x, Wk, kb, M_TOK, EQ, DIN);
    sgemm_nt<128,128,16,8,8><<<dim3(ER/128, M_TOK/128), 256>>>(x, A,  hb, M_TOK, ER, DIN);

    // Gating: one warp/token, 8 warps/block
    softmax_gate_kernel<<<M_TOK/8, 256>>>();

    // Fused output GEMM + LoRA combine + bias
    out_kernel<<<dim3(DOUT/128, M_TOK/128), 256>>>(x, W, b, Bm, out);
}

// round 3
// speedup vs baseline: 7.6571x; 7.6571x over previous
#include <cuda_runtime.h>
#include <cuda_fp16.h>
#include <cstdint>

#define M_TOK 8192
#define DIN   4096
#define DOUT  4096
#define NE    8
#define RK    16
#define EQ    256
#define ER    128
#define NPROJ 640           // EQ + EQ + ER
#define INV_SQRT_DK 0.17677669529663687f

// ---------------- scratch (no allocs allowed) ----------------
__device__ __half g_xh [(size_t)M_TOK * DIN];
__device__ __half g_Wh [(size_t)DOUT  * DIN];
__device__ __half g_Wp [(size_t)NPROJ * DIN];
__device__ __half g_Bmt[(size_t)DOUT  * ER];
__device__ float  g_proj[(size_t)M_TOK * NPROJ];
__device__ __half g_gate[(size_t)M_TOK * ER];

// ---------------- PTX helpers (base-target only: sm_80+ features) ----------
__device__ __forceinline__ uint32_t cvta_s(const void* p) {
    return (uint32_t)__cvta_generic_to_shared(p);
}
__device__ __forceinline__ void cp16(uint32_t dst, const void* src) {
    asm volatile("cp.async.cg.shared.global [%0], [%1], 16;" :: "r"(dst), "l"(src));
}
#define CP_COMMIT() asm volatile("cp.async.commit_group;" ::: "memory")
#define CP_WAIT2()  asm volatile("cp.async.wait_group 2;"  ::: "memory")

__device__ __forceinline__ void ldsm4(uint32_t& r0, uint32_t& r1,
                                      uint32_t& r2, uint32_t& r3, uint32_t addr) {
    asm volatile("ldmatrix.sync.aligned.m8n8.x4.shared.b16 {%0,%1,%2,%3}, [%4];"
                 : "=r"(r0), "=r"(r1), "=r"(r2), "=r"(r3) : "r"(addr));
}
__device__ __forceinline__ void mma16816(float* d, const uint32_t* a,
                                         uint32_t b0, uint32_t b1) {
    asm volatile(
        "mma.sync.aligned.m16n8k16.row.col.f32.f16.f16.f32 "
        "{%0,%1,%2,%3}, {%4,%5,%6,%7}, {%8,%9}, {%0,%1,%2,%3};"
        : "+f"(d[0]), "+f"(d[1]), "+f"(d[2]), "+f"(d[3])
        : "r"(a[0]), "r"(a[1]), "r"(a[2]), "r"(a[3]), "r"(b0), "r"(b1));
}

// ---------------------------------------------------------------------------
// HMMA fp16 GEMM:  C[128 x 128] (fp32) = A @ B^T  (+ gA @ gB^T over K=ER if
// LORA) (+ bias). A[M,K], B[N,K] row-major fp16, K contiguous.
// BK=32, 8 warps (2x4), warp tile 64x32. 4-slot cp.async pipeline, depth 3.
// Smem rows padded to 80B (40 halfs): ldmatrix banks 20r mod 32 -> distinct.
// ---------------------------------------------------------------------------
template<bool LORA>
__global__ __launch_bounds__(256, 2)
void gemm_hmma(const __half* __restrict__ A, const __half* __restrict__ B,
               const __half* __restrict__ gA, const __half* __restrict__ gB,
               const float* __restrict__ bias,
               float* __restrict__ C, int ldc, int K)
{
    constexpr int LDS = 40;            // halfs per smem row (32 + 8 pad)
    constexpr int AT  = 128 * LDS;     // halfs per tile
    extern __shared__ __half sm[];

    const int tid  = threadIdx.x;
    const int lane = tid & 31, wid = tid >> 5;
    const int wm = wid >> 2, wn = wid & 3;
    const int bm = blockIdx.y * 128, bn = blockIdx.x * 128;
    const int KIT = K / 32;
    const int ITERS = KIT + (LORA ? (ER / 32) : 0);

    float acc[4][4][4];
    #pragma unroll
    for (int i = 0; i < 4; i++)
        #pragma unroll
        for (int j = 0; j < 4; j++)
            #pragma unroll
            for (int v = 0; v < 4; v++) acc[i][j][v] = 0.f;

    auto load_stage = [&](int it) {
        __half* dA = sm + (it & 3) * 2 * AT;
        __half* dB = dA + AT;
        const __half *sa, *sb;
        int ld, k0;
        if (!LORA || it < KIT) { sa = A;  sb = B;  ld = K;  k0 = it * 32; }
        else                   { sa = gA; sb = gB; ld = ER; k0 = (it - KIT) * 32; }
        #pragma unroll
        for (int i = 0; i < 2; i++) {
            int c = tid + i * 256, row = c >> 2, ch = c & 3;
            cp16(cvta_s(dA + row * LDS + ch * 8),
                 sa + (size_t)(bm + row) * ld + k0 + ch * 8);
        }
        #pragma unroll
        for (int i = 0; i < 2; i++) {
            int c = tid + i * 256, row = c >> 2, ch = c & 3;
            cp16(cvta_s(dB + row * LDS + ch * 8),
                 sb + (size_t)(bn + row) * ld + k0 + ch * 8);
        }
    };

    // prologue: 3 stages in flight
    for (int it = 0; it < 3; ++it) { load_stage(it); CP_COMMIT(); }

    for (int it = 0; it < ITERS; ++it) {
        CP_WAIT2();                 // group `it` complete (<=2 newer pending)
        __syncthreads();            // all warps done with slot (it-1)&3
        if (it + 3 < ITERS) load_stage(it + 3);
        CP_COMMIT();                // commit every iter (empty ok) to keep count

        const uint32_t sa = cvta_s(sm + (it & 3) * 2 * AT);
        const uint32_t sb = sa + AT * 2;
        #pragma unroll
        for (int kp = 0; kp < 2; kp++) {
            uint32_t a[4][4], b[2][4];
            #pragma unroll
            for (int mf = 0; mf < 4; mf++) {
                int r  = wm * 64 + mf * 16 + (lane & 7) + ((lane >> 3) & 1) * 8;
                int cl = kp * 16 + ((lane >> 4) & 1) * 8;
                ldsm4(a[mf][0], a[mf][1], a[mf][2], a[mf][3],
                      sa + (r * LDS + cl) * 2);
            }
            #pragma unroll
            for (int g = 0; g < 2; g++) {
                int nr = wn * 32 + g * 16 + ((lane >> 4) & 1) * 8 + (lane & 7);
                int cl = kp * 16 + ((lane >> 3) & 1) * 8;
                ldsm4(b[g][0], b[g][1], b[g][2], b[g][3],
                      sb + (nr * LDS + cl) * 2);
            }
            #pragma unroll
            for (int mf = 0; mf < 4; mf++)
                #pragma unroll
                for (int nf = 0; nf < 4; nf++)
                    mma16816(acc[mf][nf], a[mf],
                             b[nf >> 1][(nf & 1) * 2], b[nf >> 1][(nf & 1) * 2 + 1]);
        }
    }

    // ---------------- epilogue ----------------
    #pragma unroll
    for (int mf = 0; mf < 4; mf++) {
        #pragma unroll
        for (int nf = 0; nf < 4; nf++) {
            int row = bm + wm * 64 + mf * 16 + (lane >> 2);
            int col = bn + wn * 32 + nf * 8 + (lane & 3) * 2;
            float b0 = 0.f, b1 = 0.f;
            if (bias) { b0 = bias[col]; b1 = bias[col + 1]; }
            float2 v0 = {acc[mf][nf][0] + b0, acc[mf][nf][1] + b1};
            float2 v1 = {acc[mf][nf][2] + b0, acc[mf][nf][3] + b1};
            *(float2*)(C + (size_t)row * ldc + col)       = v0;
            *(float2*)(C + (size_t)(row + 8) * ldc + col) = v1;
        }
    }
}

// ---------------------------------------------------------------------------
// conversions
// ---------------------------------------------------------------------------
__global__ void k_f2h(const float4* __restrict__ s, __half2* __restrict__ d, int n4) {
    int i = blockIdx.x * blockDim.x + threadIdx.x;
    if (i >= n4) return;
    float4 v = s[i];
    d[2 * i + 0] = __halves2half2(__float2half_rn(v.x), __float2half_rn(v.y));
    d[2 * i + 1] = __halves2half2(__float2half_rn(v.z), __float2half_rn(v.w));
}

__global__ void k_bmt(const float* __restrict__ Bm, __half* __restrict__ Bmt) {
    int idx = blockIdx.x * blockDim.x + threadIdx.x;
    if (idx >= DOUT * ER) return;
    int o = idx >> 7, j = idx & 127;
    int e = j >> 4, r = j & 15;
    Bmt[idx] = __float2half_rn(Bm[((size_t)e * DOUT + o) * RK + r]);
}

// softmax over experts + gate: g[t, e*16+r] = softmax_e(q_e.k_e/sqrt(dk)) * h[t,e,r]
__global__ __launch_bounds__(256) void k_gate() {
    int t = (blockIdx.x * 256 + threadIdx.x) >> 5;
    int lane = threadIdx.x & 31;
    if (t >= M_TOK) return;
    const float* p = g_proj + (size_t)t * NPROJ;
    float s[NE];
    #pragma unroll
    for (int e = 0; e < NE; e++) {
        float v = p[e * 32 + lane] * p[EQ + e * 32 + lane];
        #pragma unroll
        for (int o = 16; o > 0; o >>= 1) v += __shfl_xor_sync(0xffffffffu, v, o);
        s[e] = v * INV_SQRT_DK;
    }
    float m = s[0];
    #pragma unroll
    for (int e = 1; e < NE; e++) m = fmaxf(m, s[e]);
    float sum = 0.f;
    #pragma unroll
    for (int e = 0; e < NE; e++) { s[e] = expf(s[e] - m); sum += s[e]; }
    float inv = 1.f / sum;
    #pragma unroll
    for (int j = 0; j < 4; j++) {
        int er = lane * 4 + j;
        int e = er >> 4;
        g_gate[(size_t)t * ER + er] = __float2half_rn(s[e] * inv * p[2 * EQ + er]);
    }
}

// ---------------------------------------------------------------------------
extern "C" void kernel_launch(void* const* d_in, const int* in_sizes, int n_in,
                              void* d_out, int out_size) {
    const float* x  = (const float*)d_in[0];
    const float* W  = (const float*)d_in[1];
    const float* b  = (const float*)d_in[2];
    const float* Wq = (const float*)d_in[3];
    const float* Wk = (const float*)d_in[4];
    const float* A  = (const float*)d_in[5];
    const float* Bm = (const float*)d_in[6];
    float* out = (float*)d_out;

    __half *xh, *Wh, *Wp, *Bmt, *gate; float* proj;
    cudaGetSymbolAddress((void**)&xh,   g_xh);
    cudaGetSymbolAddress((void**)&Wh,   g_Wh);
    cudaGetSymbolAddress((void**)&Wp,   g_Wp);
    cudaGetSymbolAddress((void**)&Bmt,  g_Bmt);
    cudaGetSymbolAddress((void**)&gate, g_gate);
    cudaGetSymbolAddress((void**)&proj, g_proj);

    const int SMEM = 4 * 2 * 128 * 40 * 2;   // 81920 B
    cudaFuncSetAttribute(gemm_hmma<false>,
                         cudaFuncAttributeMaxDynamicSharedMemorySize, SMEM);
    cudaFuncSetAttribute(gemm_hmma<true>,
                         cudaFuncAttributeMaxDynamicSharedMemorySize, SMEM);

    // fp32 -> fp16 conversions
    k_f2h<<<(M_TOK * DIN / 4 + 255) / 256, 256>>>((const float4*)x, (__half2*)xh,
                                                  M_TOK * DIN / 4);
    k_f2h<<<(DOUT * DIN / 4 + 255) / 256, 256>>>((const float4*)W, (__half2*)Wh,
                                                 DOUT * DIN / 4);
    k_f2h<<<(EQ * DIN / 4 + 255) / 256, 256>>>((const float4*)Wq, (__half2*)Wp,
                                               EQ * DIN / 4);
    k_f2h<<<(EQ * DIN / 4 + 255) / 256, 256>>>((const float4*)Wk,
                                               (__half2*)(Wp + (size_t)EQ * DIN),
                                               EQ * DIN / 4);
    k_f2h<<<(ER * DIN / 4 + 255) / 256, 256>>>((const float4*)A,
                                               (__half2*)(Wp + (size_t)2 * EQ * DIN),
                                               ER * DIN / 4);
    k_bmt<<<(DOUT * ER + 255) / 256, 256>>>(Bm, Bmt);

    // projections: proj[8192, 640] = xh @ Wp^T
    gemm_hmma<false><<<dim3(NPROJ / 128, M_TOK / 128), 256, SMEM>>>(
        xh, Wp, nullptr, nullptr, nullptr, proj, NPROJ, DIN);

    // softmax + gating
    k_gate<<<M_TOK / 8, 256>>>();

    // fused: out = xh@Wh^T + gate@Bmt^T + bias
    gemm_hmma<true><<<dim3(DOUT / 128, M_TOK / 128), 256, SMEM>>>(
        xh, Wh, gate, Bmt, b, out, DOUT, DIN);
}